// round 11
// baseline (speedup 1.0000x reference)
#include <cuda_runtime.h>
#include <cuda_bf16.h>

// Quantum convolution: B=32, Cin=8, Cout=16, H=W=32, K=3, NQ=3, DRC=3, IT=30.
// 3-qubit statevector sim per (b, cout, cin, pixel); reduce over cin.
//
// R11: 2 pixels per thread packed as f32x2 lanes (lo=pixel p, hi=pixel p+32).
// All gate math packed (fma.rn.f32x2); gate coefficients computed packed from
// per-pixel angles; Rot matrix warp-uniform -> 8 ALU dups/gate (idle pipe).
// Keeps R10 structure: warp=cin, SU(2) gates, sparse layer 0, folded CNOTs.

#define N_B    32
#define N_CIN  8
#define N_COUT 16
#define N_IT   30
#define N_HW   32
#define N_PIX  (N_IT * N_IT)       // 900
#define N_LQ   9

#define GATE_STRIDE 36
#define IP_STRIDE   12

typedef unsigned long long u64;

__device__ __forceinline__ u64 f2pk(float lo, float hi) {
    u64 r; asm("mov.b64 %0, {%1, %2};" : "=l"(r) : "f"(lo), "f"(hi)); return r;
}
__device__ __forceinline__ u64 f2dup(float x) { return f2pk(x, x); }
__device__ __forceinline__ void f2unpk(u64 x, float& lo, float& hi) {
    asm("mov.b64 {%0, %1}, %2;" : "=f"(lo), "=f"(hi) : "l"(x));
}
__device__ __forceinline__ u64 f2mul(u64 a, u64 b) {
    u64 d; asm("mul.rn.f32x2 %0, %1, %2;" : "=l"(d) : "l"(a), "l"(b)); return d;
}
__device__ __forceinline__ u64 f2fma(u64 a, u64 b, u64 c) {
    u64 d; asm("fma.rn.f32x2 %0, %1, %2, %3;" : "=l"(d) : "l"(a), "l"(b), "l"(c)); return d;
}

// Compressed Rot: [cout][cin][lq][4: u00r,u00i,u01r,u01i]
__device__ float g_rot[N_COUT * N_CIN * N_LQ * 4];

__global__ void prep_rot_kernel(const float* __restrict__ w) {
    int t = blockIdx.x * blockDim.x + threadIdx.x;
    if (t >= N_COUT * N_CIN * N_LQ) return;
    const float* wp = w + t * 3;
    float phi = wp[0], th = wp[1], om = wp[2];
    float c, s, cp, sp, cm, sm;
    __sincosf(0.5f * th,         &s,  &c);
    __sincosf(0.5f * (phi + om), &sp, &cp);
    __sincosf(0.5f * (phi - om), &sm, &cm);
    float* o = g_rot + t * 4;
    o[0] =  cp * c;  o[1] = -sp * c;   // u00
    o[2] = -cm * s;  o[3] = -sm * s;   // u01
}

#define TILES2 ((N_PIX + 63) / 64)   // 15 tiles of 64 pixels

#define SWAP_PK(i, j) { u64 _t = sr[i]; sr[i] = sr[j]; sr[j] = _t; \
                        _t = si[i]; si[i] = si[j]; si[j] = _t; }

// Packed fused gate for gate g: coefficients car=a, cai=Im a, cnai=-Im a,
// cbr=b, cbi=Im b, cnbi=-Im b, cnbr=-Re b.  G=[[a,b],[-conj b, conj a]].
#define FUSE_GATE_PK(g) \
    u64 car, cai, cnai, cbr, cbi, cnbi, cnbr; \
    { u64 thp = f2mul(xpk[g], f2dup(prm[g])); \
      float t0_, t1_; f2unpk(thp, t0_, t1_); \
      float c0_, s0_, c1_, s1_; \
      __sincosf(t0_, &s0_, &c0_); __sincosf(t1_, &s1_, &c1_); \
      u64 cp_ = f2pk(c0_, c1_), sp_ = f2pk(s0_, s1_); \
      float4 m_ = *reinterpret_cast<const float4*>(rm + (g) * 4); \
      u64 mx_ = f2dup(m_.x),  my_ = f2dup(m_.y),  mz_ = f2dup(m_.z),  mw_ = f2dup(m_.w); \
      u64 nmx_ = f2dup(-m_.x), nmy_ = f2dup(-m_.y), nmz_ = f2dup(-m_.z), nmw_ = f2dup(-m_.w); \
      car  = f2fma(mx_,  cp_, f2mul(mz_,  sp_));  /* a  =  mx c + mz s */ \
      cai  = f2fma(my_,  cp_, f2mul(mw_,  sp_)); \
      cnai = f2fma(nmy_, cp_, f2mul(nmw_, sp_)); \
      cbr  = f2fma(mz_,  cp_, f2mul(nmx_, sp_));  /* b  =  mz c - mx s */ \
      cbi  = f2fma(mw_,  cp_, f2mul(nmy_, sp_)); \
      cnbi = f2fma(nmw_, cp_, f2mul(my_,  sp_)); \
      cnbr = f2fma(nmz_, cp_, f2mul(mx_,  sp_)); }

// Packed SU(2) pair apply.
#define PAIR_APPLY_PK(i0, i1) { \
    u64 x0r = sr[i0], x0i = si[i0], x1r = sr[i1], x1i = si[i1]; \
    sr[i0] = f2fma(car, x0r, f2fma(cnai, x0i, f2fma(cbr,  x1r, f2mul(cnbi, x1i)))); \
    si[i0] = f2fma(car, x0i, f2fma(cai,  x0r, f2fma(cbr,  x1i, f2mul(cbi,  x1r)))); \
    sr[i1] = f2fma(car, x1r, f2fma(cai,  x1i, f2fma(cnbr, x0r, f2mul(cnbi, x0i)))); \
    si[i1] = f2fma(car, x1i, f2fma(cnai, x1r, f2fma(cnbr, x0i, f2mul(cbi,  x0r)))); }

__global__ void __launch_bounds__(256, 3)
qconv_kernel(const float* __restrict__ inp,   // (32,8,32,32)
             const float* __restrict__ ip,    // (16,8,3,3)
             float* __restrict__ out)         // (32,16,30,30)
{
    __shared__ float s_ip[N_CIN * IP_STRIDE];
    __shared__ __align__(16) float s_gate[N_CIN * GATE_STRIDE];
    __shared__ float s_red[512];

    int bid  = blockIdx.x;
    int tile = bid % TILES2;
    int bc   = bid / TILES2;
    int cout = bc % N_COUT;
    int b    = bc / N_COUT;
    int tid  = threadIdx.x;

    for (int i = tid; i < N_CIN * N_LQ; i += 256) {
        int ci = i / N_LQ, j = i % N_LQ;
        s_ip[ci * IP_STRIDE + j] = 0.5f * ip[cout * (N_CIN * N_LQ) + i];
    }
    for (int i = tid; i < N_CIN * N_LQ * 4; i += 256) {
        int ci = i / (N_LQ * 4), j = i % (N_LQ * 4);
        s_gate[ci * GATE_STRIDE + j] = g_rot[cout * (N_CIN * N_LQ * 4) + i];
    }
    __syncthreads();

    int cin  = tid >> 5;
    int lane = tid & 31;
    int p0 = tile * 64 + lane;          // lo lane pixel
    int p1 = p0 + 32;                   // hi lane pixel
    int pc0 = p0 < N_PIX ? p0 : N_PIX - 1;
    int pc1 = p1 < N_PIX ? p1 : N_PIX - 1;
    int ii0 = pc0 / N_IT, jj0 = pc0 % N_IT;
    int ii1 = pc1 / N_IT, jj1 = pc1 % N_IT;

    const float* xb = inp + (b * N_CIN + cin) * (N_HW * N_HW);
    u64 xpk[9];
#pragma unroll
    for (int l = 0; l < 3; l++)
#pragma unroll
        for (int q = 0; q < 3; q++) {
            float v0 = __ldg(xb + (ii0 + l) * N_HW + jj0 + q);
            float v1 = __ldg(xb + (ii1 + l) * N_HW + jj1 + q);
            xpk[l * 3 + q] = f2pk(v0, v1);
        }

    const float* prm = s_ip   + cin * IP_STRIDE;   // warp-uniform
    const float* rm  = s_gate + cin * GATE_STRIDE; // warp-uniform

    u64 sr[8], si[8];

    // ---------- Layer 0: sparse from |000> (packed) ----------
    {
        FUSE_GATE_PK(0);
        u64 q0r = car,  q0i = cai;    // amp0 = a
        u64 q4r = cnbr, q4i = cbi;    // amp4 = -conj(b)

        u64 d0r, d0i, d2r, d2i, d4r, d4i, d6r, d6i;
        {
            FUSE_GATE_PK(1);
            d0r = f2fma(car,  q0r, f2mul(cnai, q0i));
            d0i = f2fma(car,  q0i, f2mul(cai,  q0r));
            d2r = f2fma(cnbr, q0r, f2mul(cnbi, q0i));
            d2i = f2fma(cnbr, q0i, f2mul(cbi,  q0r));
            d4r = f2fma(car,  q4r, f2mul(cnai, q4i));
            d4i = f2fma(car,  q4i, f2mul(cai,  q4r));
            d6r = f2fma(cnbr, q4r, f2mul(cnbi, q4i));
            d6i = f2fma(cnbr, q4i, f2mul(cbi,  q4r));
        }
        {
            FUSE_GATE_PK(2);
            u64 c0r = f2fma(car,  d0r, f2mul(cnai, d0i));
            u64 c0i = f2fma(car,  d0i, f2mul(cai,  d0r));
            u64 c1r = f2fma(cnbr, d0r, f2mul(cnbi, d0i));
            u64 c1i = f2fma(cnbr, d0i, f2mul(cbi,  d0r));
            u64 c2r = f2fma(car,  d2r, f2mul(cnai, d2i));
            u64 c2i = f2fma(car,  d2i, f2mul(cai,  d2r));
            u64 c3r = f2fma(cnbr, d2r, f2mul(cnbi, d2i));
            u64 c3i = f2fma(cnbr, d2i, f2mul(cbi,  d2r));
            u64 c4r = f2fma(car,  d4r, f2mul(cnai, d4i));
            u64 c4i = f2fma(car,  d4i, f2mul(cai,  d4r));
            u64 c5r = f2fma(cnbr, d4r, f2mul(cnbi, d4i));
            u64 c5i = f2fma(cnbr, d4i, f2mul(cbi,  d4r));
            u64 c6r = f2fma(car,  d6r, f2mul(cnai, d6i));
            u64 c6i = f2fma(car,  d6i, f2mul(cai,  d6r));
            u64 c7r = f2fma(cnbr, d6r, f2mul(cnbi, d6i));
            u64 c7i = f2fma(cnbr, d6i, f2mul(cbi,  d6r));

            // layer-0 CNOT ring folded: s[i] = c[t[i]], t=[0,7,3,4,6,1,5,2]
            sr[0] = c0r; si[0] = c0i;   sr[1] = c7r; si[1] = c7i;
            sr[2] = c3r; si[2] = c3i;   sr[3] = c4r; si[3] = c4i;
            sr[4] = c6r; si[4] = c6i;   sr[5] = c1r; si[5] = c1i;
            sr[6] = c5r; si[6] = c5i;   sr[7] = c2r; si[7] = c2i;
        }
    }

    // ---------- Layer 1 ----------
    {
        FUSE_GATE_PK(3);   // wire 0
        PAIR_APPLY_PK(0, 4); PAIR_APPLY_PK(1, 5);
        PAIR_APPLY_PK(2, 6); PAIR_APPLY_PK(3, 7);
    }
    {
        FUSE_GATE_PK(4);   // wire 1
        PAIR_APPLY_PK(0, 2); PAIR_APPLY_PK(1, 3);
        PAIR_APPLY_PK(4, 6); PAIR_APPLY_PK(5, 7);
    }
    {
        FUSE_GATE_PK(5);   // wire 2
        PAIR_APPLY_PK(0, 1); PAIR_APPLY_PK(2, 3);
        PAIR_APPLY_PK(4, 5); PAIR_APPLY_PK(6, 7);
    }
    // mid CNOT ring (u64 renames, free)
    SWAP_PK(4, 6); SWAP_PK(5, 7);
    SWAP_PK(2, 3); SWAP_PK(6, 7);
    SWAP_PK(1, 5); SWAP_PK(3, 7);

    // ---------- Layer 2 (final CNOT folded into measurement signs) ----------
    {
        FUSE_GATE_PK(6);
        PAIR_APPLY_PK(0, 4); PAIR_APPLY_PK(1, 5);
        PAIR_APPLY_PK(2, 6); PAIR_APPLY_PK(3, 7);
    }
    {
        FUSE_GATE_PK(7);
        PAIR_APPLY_PK(0, 2); PAIR_APPLY_PK(1, 3);
        PAIR_APPLY_PK(4, 6); PAIR_APPLY_PK(5, 7);
    }
    {
        FUSE_GATE_PK(8);
        PAIR_APPLY_PK(0, 1); PAIR_APPLY_PK(2, 3);
        PAIR_APPLY_PK(4, 5); PAIR_APPLY_PK(6, 7);
    }

    // measurement: positives {0,3,5,6}, negatives {1,2,4,7}
    u64 pp = f2mul(sr[0], sr[0]);
    pp = f2fma(si[0], si[0], pp);
    pp = f2fma(sr[3], sr[3], pp);  pp = f2fma(si[3], si[3], pp);
    pp = f2fma(sr[5], sr[5], pp);  pp = f2fma(si[5], si[5], pp);
    pp = f2fma(sr[6], sr[6], pp);  pp = f2fma(si[6], si[6], pp);
    u64 nn = f2mul(sr[1], sr[1]);
    nn = f2fma(si[1], si[1], nn);
    nn = f2fma(sr[2], sr[2], nn);  nn = f2fma(si[2], si[2], nn);
    nn = f2fma(sr[4], sr[4], nn);  nn = f2fma(si[4], si[4], nn);
    nn = f2fma(sr[7], sr[7], nn);  nn = f2fma(si[7], si[7], nn);
    float pl, ph, nl, nh;
    f2unpk(pp, pl, ph);
    f2unpk(nn, nl, nh);
    float e0 = pl - nl;   // pixel p0
    float e1 = ph - nh;   // pixel p1

    // cin-reduction via smem (bank = lane, conflict-free)
    s_red[cin * 64 + lane]      = e0;
    s_red[cin * 64 + 32 + lane] = e1;
    __syncthreads();

    if (tid < 64) {
        float acc = 0.0f;
#pragma unroll
        for (int w = 0; w < N_CIN; w++)
            acc += s_red[w * 64 + tid];
        int po = tile * 64 + tid;
        if (po < N_PIX)
            out[(b * N_COUT + cout) * N_PIX + po] = acc;   // coalesced
    }
}

extern "C" void kernel_launch(void* const* d_in, const int* in_sizes, int n_in,
                              void* d_out, int out_size) {
    const float* inputs       = (const float*)d_in[0];  // (32,8,32,32)
    const float* input_params = (const float*)d_in[1];  // (16,8,3,3)
    const float* weights      = (const float*)d_in[2];  // (16,8,3,3,3)
    float* out = (float*)d_out;                         // (32,16,30,30)

    prep_rot_kernel<<<(N_COUT * N_CIN * N_LQ + 255) / 256, 256>>>(weights);

    int grid = N_B * N_COUT * TILES2;   // 32*16*15 = 7680
    qconv_kernel<<<grid, 256>>>(inputs, input_params, out);
}